// round 1
// baseline (speedup 1.0000x reference)
#include <cuda_runtime.h>
#include <math_constants.h>

#define NROWS 2048
#define DIN   256
#define DPROJ 256   // Q[0:64) K[64:128) V[128:192) R[192:256)
#define DK    64
#define DR    64
#define DV    64

// Scratch for the projection (2048 x 256 fp32 = 2 MB). Device global => allowed.
__device__ float g_proj[NROWS * DPROJ];

// ---------------------------------------------------------------------------
// Kernel 1: proj = H @ W^T   (2048x256) = (2048x256) @ (256x256)^T
// Classic 64x64x16 smem-tiled fp32 GEMM, 4x4 register micro-tile, 256 threads.
// ---------------------------------------------------------------------------
__global__ __launch_bounds__(256) void proj_gemm_kernel(
    const float* __restrict__ H, const float* __restrict__ W)
{
    const int BM = 64, BN = 64, BK = 16;
    __shared__ float As[BM][BK + 1];
    __shared__ float Bs[BN][BK + 1];

    const int tx = threadIdx.x & 15;        // 0..15 -> N micro-tiles
    const int ty = threadIdx.x >> 4;        // 0..15 -> M micro-tiles
    const int bm = blockIdx.y * BM;
    const int bn = blockIdx.x * BN;

    float acc[4][4];
#pragma unroll
    for (int a = 0; a < 4; a++)
#pragma unroll
        for (int b = 0; b < 4; b++) acc[a][b] = 0.f;

    const int t   = threadIdx.x;
    const int row = t >> 2;          // 0..63
    const int cg  = (t & 3) * 4;     // 0,4,8,12

    for (int k0 = 0; k0 < DIN; k0 += BK) {
        float4 a4 = *(const float4*)&H[(size_t)(bm + row) * DIN + k0 + cg];
        As[row][cg + 0] = a4.x; As[row][cg + 1] = a4.y;
        As[row][cg + 2] = a4.z; As[row][cg + 3] = a4.w;
        float4 b4 = *(const float4*)&W[(size_t)(bn + row) * DIN + k0 + cg];
        Bs[row][cg + 0] = b4.x; Bs[row][cg + 1] = b4.y;
        Bs[row][cg + 2] = b4.z; Bs[row][cg + 3] = b4.w;
        __syncthreads();

#pragma unroll
        for (int k = 0; k < BK; k++) {
            float af[4], bf[4];
#pragma unroll
            for (int a = 0; a < 4; a++) af[a] = As[ty * 4 + a][k];
#pragma unroll
            for (int b = 0; b < 4; b++) bf[b] = Bs[tx * 4 + b][k];
#pragma unroll
            for (int a = 0; a < 4; a++)
#pragma unroll
                for (int b = 0; b < 4; b++) acc[a][b] = fmaf(af[a], bf[b], acc[a][b]);
        }
        __syncthreads();
    }

#pragma unroll
    for (int a = 0; a < 4; a++)
#pragma unroll
        for (int b = 0; b < 4; b++)
            g_proj[(size_t)(bm + ty * 4 + a) * DPROJ + bn + tx * 4 + b] = acc[a][b];
}

// ---------------------------------------------------------------------------
// Kernel 2: fused  S[i,j] = scale*(Q[i].K[j] + R[i].D[i,j]),
//           softmax over j, O[i] = sum_j softmax * V[j]
// One CTA per row i, 8 warps, each warp owns a contiguous 256-key chunk.
// Per j: lane l loads D[i,j,2l:2l+2] (coalesced 256B/warp, DRAM stream),
// K/V float2 from L2-resident proj; single fused shfl-xor dot reduction;
// per-warp online softmax; 8-way smem combine at the end.
// ---------------------------------------------------------------------------
__global__ __launch_bounds__(256) void attn_fused_kernel(
    const float* __restrict__ D, float* __restrict__ out)
{
    const int i    = blockIdx.x;
    const int lane = threadIdx.x & 31;
    const int warp = threadIdx.x >> 5;
    const float scale = 0.08838834764831845f;  // 1/sqrt(DK+DR) = 1/sqrt(128)

    const float2 q2 = *(const float2*)&g_proj[(size_t)i * DPROJ + 2 * lane];
    const float2 r2 = *(const float2*)&g_proj[(size_t)i * DPROJ + 192 + 2 * lane];
    const float* Drow = D + (size_t)i * NROWS * DR;

    float  m   = -CUDART_INF_F;
    float  l   = 0.f;
    float2 acc = make_float2(0.f, 0.f);

    const int jbase = warp * 256;

#pragma unroll 1
    for (int jt = 0; jt < 256; jt += 4) {
        const int j = jbase + jt;
        float  s[4];
        float2 v[4];
#pragma unroll
        for (int u = 0; u < 4; u++) {
            float2 d2 = *(const float2*)&Drow[(size_t)(j + u) * DR + 2 * lane];
            float2 k2 = *(const float2*)&g_proj[(size_t)(j + u) * DPROJ + 64 + 2 * lane];
            v[u]      = *(const float2*)&g_proj[(size_t)(j + u) * DPROJ + 128 + 2 * lane];
            s[u] = d2.x * r2.x + d2.y * r2.y + k2.x * q2.x + k2.y * q2.y;
        }
#pragma unroll
        for (int o = 16; o > 0; o >>= 1) {
#pragma unroll
            for (int u = 0; u < 4; u++)
                s[u] += __shfl_xor_sync(0xffffffffu, s[u], o);
        }
        float mnew = m;
#pragma unroll
        for (int u = 0; u < 4; u++) {
            s[u] *= scale;
            mnew = fmaxf(mnew, s[u]);
        }
        const float c = __expf(m - mnew);
        float w[4];
#pragma unroll
        for (int u = 0; u < 4; u++) w[u] = __expf(s[u] - mnew);

        l = l * c + (w[0] + w[1]) + (w[2] + w[3]);
        float ax = acc.x * c, ay = acc.y * c;
#pragma unroll
        for (int u = 0; u < 4; u++) {
            ax = fmaf(w[u], v[u].x, ax);
            ay = fmaf(w[u], v[u].y, ay);
        }
        acc.x = ax; acc.y = ay;
        m = mnew;
    }

    // ---- cross-warp combine ----
    __shared__ float sm_m[8];
    __shared__ float sm_l[8];
    __shared__ float sm_acc[8][DV];

    if (lane == 0) { sm_m[warp] = m; sm_l[warp] = l; }
    sm_acc[warp][2 * lane + 0] = acc.x;
    sm_acc[warp][2 * lane + 1] = acc.y;
    __syncthreads();

    if (threadIdx.x < DV) {
        const int d = threadIdx.x;
        float M = sm_m[0];
#pragma unroll
        for (int w = 1; w < 8; w++) M = fmaxf(M, sm_m[w]);
        float L = 0.f, o = 0.f;
#pragma unroll
        for (int w = 0; w < 8; w++) {
            const float cc = __expf(sm_m[w] - M);
            L = fmaf(sm_l[w], cc, L);
            o = fmaf(sm_acc[w][d], cc, o);
        }
        out[(size_t)i * DV + d] = o / L;
    }
}

// ---------------------------------------------------------------------------
extern "C" void kernel_launch(void* const* d_in, const int* in_sizes, int n_in,
                              void* d_out, int out_size)
{
    const float* H = (const float*)d_in[0];   // (2048, 256)
    const float* D = (const float*)d_in[1];   // (2048, 2048, 64)
    const float* W = (const float*)d_in[2];   // (256, 256)
    float* out = (float*)d_out;               // (2048, 64)

    dim3 g1(DPROJ / 64, NROWS / 64);          // (4, 32)
    proj_gemm_kernel<<<g1, 256>>>(H, W);
    attn_fused_kernel<<<NROWS, 256>>>(D, out);
}

// round 2
// speedup vs baseline: 1.0534x; 1.0534x over previous
#include <cuda_runtime.h>
#include <math_constants.h>

#define NROWS 2048
#define DIN   256
#define DPROJ 256   // Q[0:64) K[64:128) V[128:192) R[192:256)
#define DK    64
#define DR    64
#define DV    64

// Scratch for the projection (2048 x 256 fp32 = 2 MB). Device global => allowed.
__device__ float g_proj[NROWS * DPROJ];

// ---------------------------------------------------------------------------
// Kernel 1: proj = H @ W^T   (2048x256) = (2048x256) @ (256x256)^T
// 64x64x32 smem-tiled fp32 GEMM, 4x4 register micro-tile, 256 threads.
// ---------------------------------------------------------------------------
__global__ __launch_bounds__(256) void proj_gemm_kernel(
    const float* __restrict__ H, const float* __restrict__ W)
{
    const int BM = 64, BN = 64, BK = 32;
    __shared__ float As[BM][BK + 1];
    __shared__ float Bs[BN][BK + 1];

    const int tx = threadIdx.x & 15;        // 0..15 -> N micro-tiles
    const int ty = threadIdx.x >> 4;        // 0..15 -> M micro-tiles
    const int bm = blockIdx.y * BM;
    const int bn = blockIdx.x * BN;

    float acc[4][4];
#pragma unroll
    for (int a = 0; a < 4; a++)
#pragma unroll
        for (int b = 0; b < 4; b++) acc[a][b] = 0.f;

    const int t   = threadIdx.x;
    const int row = t >> 2;          // 0..63
    const int cg  = (t & 3) * 8;     // 0,8,16,24

    for (int k0 = 0; k0 < DIN; k0 += BK) {
#pragma unroll
        for (int h = 0; h < 2; h++) {
            float4 a4 = *(const float4*)&H[(size_t)(bm + row) * DIN + k0 + cg + 4 * h];
            As[row][cg + 4 * h + 0] = a4.x; As[row][cg + 4 * h + 1] = a4.y;
            As[row][cg + 4 * h + 2] = a4.z; As[row][cg + 4 * h + 3] = a4.w;
            float4 b4 = *(const float4*)&W[(size_t)(bn + row) * DIN + k0 + cg + 4 * h];
            Bs[row][cg + 4 * h + 0] = b4.x; Bs[row][cg + 4 * h + 1] = b4.y;
            Bs[row][cg + 4 * h + 2] = b4.z; Bs[row][cg + 4 * h + 3] = b4.w;
        }
        __syncthreads();

#pragma unroll
        for (int k = 0; k < BK; k++) {
            float af[4], bf[4];
#pragma unroll
            for (int a = 0; a < 4; a++) af[a] = As[ty * 4 + a][k];
#pragma unroll
            for (int b = 0; b < 4; b++) bf[b] = Bs[tx * 4 + b][k];
#pragma unroll
            for (int a = 0; a < 4; a++)
#pragma unroll
                for (int b = 0; b < 4; b++) acc[a][b] = fmaf(af[a], bf[b], acc[a][b]);
        }
        __syncthreads();
    }

#pragma unroll
    for (int a = 0; a < 4; a++)
#pragma unroll
        for (int b = 0; b < 4; b++)
            g_proj[(size_t)(bm + ty * 4 + a) * DPROJ + bn + tx * 4 + b] = acc[a][b];
}

// ---------------------------------------------------------------------------
// Kernel 2: fused  S[i,j] = scale*(Q[i].K[j] + R[i].D[i,j]),
//           softmax over j, O[i] = sum_j softmax * V[j]
//
// One CTA per row i, 8 warps. Each warp is split into two 16-lane GROUPS
// (h = lane>>4); each group keeps its own online-softmax state and handles
// the keys j = jbase + jt + 2u + h. Lane owns dims [4*(lane&15), +4):
//   - D/K/V are LDG.128 (one wide load per 2 keys per operand)
//   - dot reduction is a 4-level shfl-xor (1,2,4,8) confined to the group;
//     the reduced s is replicated across the group, so the softmax weight
//     needs no broadcast.
// Final combine over 16 group-partials through smem.
// ---------------------------------------------------------------------------
__global__ __launch_bounds__(256) void attn_fused_kernel(
    const float* __restrict__ D, float* __restrict__ out)
{
    const int i    = blockIdx.x;
    const int lane = threadIdx.x & 31;
    const int warp = threadIdx.x >> 5;
    const int h    = lane >> 4;        // group within warp
    const int lx   = lane & 15;        // lane within group -> dims 4*lx..4*lx+3
    const float scale = 0.08838834764831845f;  // 1/sqrt(DK+DR) = 1/sqrt(128)

    const float4 q4 = *(const float4*)&g_proj[(size_t)i * DPROJ + 4 * lx];
    const float4 r4 = *(const float4*)&g_proj[(size_t)i * DPROJ + 192 + 4 * lx];
    const float* Drow = D + (size_t)i * NROWS * DR;

    float  m = -CUDART_INF_F;
    float  l = 0.f;
    float4 acc = make_float4(0.f, 0.f, 0.f, 0.f);

    const int jbase = warp * 256;

#pragma unroll 1
    for (int jt = 0; jt < 256; jt += 4) {
        float4 d4[2], k4[2], v4[2];
        float  s[2];
#pragma unroll
        for (int u = 0; u < 2; u++) {
            const int j = jbase + jt + 2 * u + h;
            d4[u] = *(const float4*)&Drow[(size_t)j * DR + 4 * lx];
            k4[u] = *(const float4*)&g_proj[(size_t)j * DPROJ + 64 + 4 * lx];
            v4[u] = *(const float4*)&g_proj[(size_t)j * DPROJ + 128 + 4 * lx];
        }
#pragma unroll
        for (int u = 0; u < 2; u++) {
            float t0 = d4[u].x * r4.x;
            t0 = fmaf(d4[u].y, r4.y, t0);
            t0 = fmaf(d4[u].z, r4.z, t0);
            t0 = fmaf(d4[u].w, r4.w, t0);
            t0 = fmaf(k4[u].x, q4.x, t0);
            t0 = fmaf(k4[u].y, q4.y, t0);
            t0 = fmaf(k4[u].z, q4.z, t0);
            t0 = fmaf(k4[u].w, q4.w, t0);
            s[u] = t0;
        }
        // 4-level butterfly, stays within each 16-lane group (bit 4 untouched)
#pragma unroll
        for (int o = 1; o < 16; o <<= 1) {
            s[0] += __shfl_xor_sync(0xffffffffu, s[0], o);
            s[1] += __shfl_xor_sync(0xffffffffu, s[1], o);
        }
        s[0] *= scale;
        s[1] *= scale;

        const float mnew = fmaxf(m, fmaxf(s[0], s[1]));
        const float c  = __expf(m - mnew);
        const float w0 = __expf(s[0] - mnew);
        const float w1 = __expf(s[1] - mnew);

        l = fmaf(l, c, w0 + w1);
        acc.x = fmaf(w1, v4[1].x, fmaf(w0, v4[0].x, acc.x * c));
        acc.y = fmaf(w1, v4[1].y, fmaf(w0, v4[0].y, acc.y * c));
        acc.z = fmaf(w1, v4[1].z, fmaf(w0, v4[0].z, acc.z * c));
        acc.w = fmaf(w1, v4[1].w, fmaf(w0, v4[0].w, acc.w * c));
        m = mnew;
    }

    // ---- combine 16 group-partials ----
    __shared__ float sm_m[16];
    __shared__ float sm_l[16];
    __shared__ float sm_acc[16][DV];

    const int g = warp * 2 + h;
    if (lx == 0) { sm_m[g] = m; sm_l[g] = l; }
    *(float4*)&sm_acc[g][4 * lx] = acc;
    __syncthreads();

    if (threadIdx.x < DV) {
        const int d = threadIdx.x;
        float M = sm_m[0];
#pragma unroll
        for (int w = 1; w < 16; w++) M = fmaxf(M, sm_m[w]);
        float L = 0.f, o = 0.f;
#pragma unroll
        for (int w = 0; w < 16; w++) {
            const float cc = __expf(sm_m[w] - M);
            L = fmaf(sm_l[w], cc, L);
            o = fmaf(sm_acc[w][d], cc, o);
        }
        out[(size_t)i * DV + d] = o / L;
    }
}

// ---------------------------------------------------------------------------
extern "C" void kernel_launch(void* const* d_in, const int* in_sizes, int n_in,
                              void* d_out, int out_size)
{
    const float* H = (const float*)d_in[0];   // (2048, 256)
    const float* D = (const float*)d_in[1];   // (2048, 2048, 64)
    const float* W = (const float*)d_in[2];   // (256, 256)
    float* out = (float*)d_out;               // (2048, 64)

    dim3 g1(DPROJ / 64, NROWS / 64);          // (4, 32)
    proj_gemm_kernel<<<g1, 256>>>(H, W);
    attn_fused_kernel<<<NROWS, 256>>>(D, out);
}